// round 1
// baseline (speedup 1.0000x reference)
#include <cuda_runtime.h>
#include <cstdint>

#define BB 2
#define SS 2048
#define DM 1024
#define HH 8
#define HD 64
#define NREL 8
#define MTOT (BB*SS)          // 4096 rows (b,s flattened)
#define PLD 3584              // fused projection row stride (7*512)

// ---------------- scratch (device globals; no allocation allowed) ----------------
static __device__ float g_wcat[(size_t)7*512*DM];                 // 14 MB
static __device__ float g_proj[(size_t)MTOT*PLD];                 // 59 MB
static __device__ float g_sv[(size_t)MTOT*512];                   // 8.4 MB
static __device__ float g_sc_sa[(size_t)BB*HH*SS*SS];             // 268 MB (scores -> alpha in place)
static __device__ float g_sc_ra[(size_t)BB*HH*SS*SS];             // 268 MB
static __device__ float g_rel[(size_t)BB*NREL*SS*SS];             // 268 MB
static __device__ float g_ctx_sa[(size_t)MTOT*512];               // 8.4 MB
static __device__ float g_ctx_ra[(size_t)MTOT*512];               // 8.4 MB
static __device__ float g_attrel[(size_t)MTOT*64];                // 1 MB

// ---------------- generic tiled SGEMM: C = scale * A (M,K) * op(B) ----------------
// TRANSB=true : B is (N,K) row-major (NT gemm, C[m,n] = sum_k A[m,k]*B[n,k])
// TRANSB=false: B is (K,N) row-major (NN gemm, C[m,n] = sum_k A[m,k]*B[k,n])
// CAUSAL: skip blocks entirely above the diagonal (BM==BN)
// KCLAMP: limit K loop to min(K, m0+BM)  (for alpha@V where alpha is causal)
#define BM 128
#define BN 128
#define BKG 8

template<bool TRANSB, bool CAUSAL, bool KCLAMP>
__global__ __launch_bounds__(256)
void gemm_k(const float* __restrict__ A, int lda, long long sAo, long long sAi,
            const float* __restrict__ B, int ldb, long long sBo, long long sBi,
            float* __restrict__ C, int ldc, long long sCo, long long sCi,
            int M, int N, int K, int inner, float scale)
{
    int bx = blockIdx.x, by = blockIdx.y, bz = blockIdx.z;
    if (CAUSAL && bx > by) return;
    int outer = bz / inner, in = bz % inner;
    A += outer * sAo + (long long)in * sAi;
    B += outer * sBo + (long long)in * sBi;
    C += outer * sCo + (long long)in * sCi;
    int m0 = by * BM, n0 = bx * BN;
    int kend = K;
    if (KCLAMP) kend = min(K, m0 + BM);

    __shared__ float As[BKG][BM];
    __shared__ float Bs[BKG][BN + 4];

    int tid = threadIdx.x;
    int tx = tid & 15, ty = tid >> 4;

    float acc[8][8];
#pragma unroll
    for (int i = 0; i < 8; i++)
#pragma unroll
        for (int j = 0; j < 8; j++) acc[i][j] = 0.0f;

    int arow = tid >> 1;             // 0..127
    int akq  = (tid & 1) * 4;        // 0 or 4
    int bk_nn = tid >> 5;            // 0..7
    int bn_nn = (tid & 31) * 4;      // 0..124

    for (int k0 = 0; k0 < kend; k0 += BKG) {
        // ---- load A tile (BM x BKG), transposed into As[k][m]
        float4 av = make_float4(0.f, 0.f, 0.f, 0.f);
        if (m0 + arow < M)
            av = *(const float4*)(A + (size_t)(m0 + arow) * lda + k0 + akq);
        As[akq + 0][arow] = av.x;
        As[akq + 1][arow] = av.y;
        As[akq + 2][arow] = av.z;
        As[akq + 3][arow] = av.w;

        if (TRANSB) {
            float4 bv = make_float4(0.f, 0.f, 0.f, 0.f);
            if (n0 + arow < N)
                bv = *(const float4*)(B + (size_t)(n0 + arow) * ldb + k0 + akq);
            Bs[akq + 0][arow] = bv.x;
            Bs[akq + 1][arow] = bv.y;
            Bs[akq + 2][arow] = bv.z;
            Bs[akq + 3][arow] = bv.w;
        } else {
            float4 bv = make_float4(0.f, 0.f, 0.f, 0.f);
            if (n0 + bn_nn < N)
                bv = *(const float4*)(B + (size_t)(k0 + bk_nn) * ldb + n0 + bn_nn);
            *(float4*)&Bs[bk_nn][bn_nn] = bv;
        }
        __syncthreads();

#pragma unroll
        for (int kk = 0; kk < BKG; kk++) {
            float a[8], b[8];
            *(float4*)(a)     = *(const float4*)&As[kk][ty * 4];
            *(float4*)(a + 4) = *(const float4*)&As[kk][64 + ty * 4];
            *(float4*)(b)     = *(const float4*)&Bs[kk][tx * 4];
            *(float4*)(b + 4) = *(const float4*)&Bs[kk][64 + tx * 4];
#pragma unroll
            for (int i = 0; i < 8; i++)
#pragma unroll
                for (int j = 0; j < 8; j++)
                    acc[i][j] += a[i] * b[j];
        }
        __syncthreads();
    }

    // ---- store
#pragma unroll
    for (int ih = 0; ih < 2; ih++) {
#pragma unroll
        for (int r = 0; r < 4; r++) {
            int m = m0 + ih * 64 + ty * 4 + r;
            if (m < M) {
                float* crow = C + (size_t)m * ldc;
#pragma unroll
                for (int jh = 0; jh < 2; jh++) {
                    int n = n0 + jh * 64 + tx * 4;
                    if (n < N) {
                        float4 v;
                        v.x = acc[ih * 4 + r][jh * 4 + 0] * scale;
                        v.y = acc[ih * 4 + r][jh * 4 + 1] * scale;
                        v.z = acc[ih * 4 + r][jh * 4 + 2] * scale;
                        v.w = acc[ih * 4 + r][jh * 4 + 3] * scale;
                        *(float4*)(crow + n) = v;
                    }
                }
            }
        }
    }
}

// ---------------- weight concat: 7 x (512,1024) -> g_wcat (3584,1024) ----------------
__global__ void copy_wcat_k(const float* __restrict__ w0, const float* __restrict__ w1,
                            const float* __restrict__ w2, const float* __restrict__ w3,
                            const float* __restrict__ w4, const float* __restrict__ w5,
                            const float* __restrict__ w6, float* __restrict__ dst)
{
    size_t idx = (size_t)blockIdx.x * blockDim.x + threadIdx.x;
    const size_t per = (size_t)512 * DM;
    if (idx >= 7 * per) return;
    int p = (int)(idx / per);
    size_t off = idx % per;
    const float* w = w0;
    if (p == 1) w = w1; else if (p == 2) w = w2; else if (p == 3) w = w3;
    else if (p == 4) w = w4; else if (p == 5) w = w5; else if (p == 6) w = w6;
    dst[idx] = w[off];
}

// ---------------- RoPE on slabs {0:q_sa, 1:k_sa, 3:qa, 4:ka} of g_proj ----------------
__global__ void rope_k(float* __restrict__ proj, const float* __restrict__ fc,
                       const float* __restrict__ fs)
{
    size_t idx = (size_t)blockIdx.x * blockDim.x + threadIdx.x;
    // idx = (((row*4 + p)*8 + h)*32 + m)
    int m = idx & 31;
    int h = (idx >> 5) & 7;
    int p = (idx >> 8) & 3;
    size_t row = idx >> 10;
    if (row >= (size_t)MTOT) return;
    int s = (int)(row & (SS - 1));
    int pc = (p < 2) ? p : p + 1;     // {0,1,3,4}
    float* base = proj + row * PLD + pc * 512 + h * 64 + 2 * m;
    float c = fc[s * 32 + m];
    float sn = fs[s * 32 + m];
    float xr = base[0], xi = base[1];
    base[0] = xr * c - xi * sn;
    base[1] = xr * sn + xi * c;
}

// ---------------- in-place causal row softmax on (G, S, S) ----------------
__global__ void softmax_k(float* __restrict__ sc)
{
    int i = blockIdx.x;
    long long g = blockIdx.y;
    float* row = sc + (g * SS + (long long)i) * SS;
    int t = threadIdx.x;
    const int C = SS / 256;
    float vals[C];
    float mx = -3.4e38f;
#pragma unroll
    for (int c = 0; c < C; c++) {
        int j = t + c * 256;
        float v = (j <= i) ? row[j] : -3.4e38f;
        vals[c] = v;
        mx = fmaxf(mx, v);
    }
    __shared__ float red[256];
    red[t] = mx; __syncthreads();
    for (int o = 128; o > 0; o >>= 1) { if (t < o) red[t] = fmaxf(red[t], red[t + o]); __syncthreads(); }
    mx = red[0];
    __syncthreads();
    float sum = 0.f;
#pragma unroll
    for (int c = 0; c < C; c++) {
        float e = __expf(vals[c] - mx);
        vals[c] = e;
        sum += e;
    }
    red[t] = sum; __syncthreads();
    for (int o = 128; o > 0; o >>= 1) { if (t < o) red[t] += red[t + o]; __syncthreads(); }
    float inv = 1.0f / red[0];
#pragma unroll
    for (int c = 0; c < C; c++) {
        int j = t + c * 256;
        row[j] = vals[c] * inv;
    }
}

// ---------------- attended_rel[b,i,h,r] = sum_{j<=i} alpha[b,h,i,j] * rel[b,r,i,j] ----------------
__global__ void attrel_k(const float* __restrict__ alpha, const float* __restrict__ rel,
                         float* __restrict__ out)
{
    int i = blockIdx.x, b = blockIdx.y;
    int t = threadIdx.x;
    int o = t >> 2, stripe = t & 3;     // o = h*8 + r
    int h = o >> 3, r = o & 7;
    const float* arow = alpha + ((long long)(b * HH + h) * SS + i) * SS;
    const float* rrow = rel   + ((long long)(b * NREL + r) * SS + i) * SS;
    float acc = 0.f;
    for (int j = stripe; j <= i; j += 4) acc += arow[j] * rrow[j];
    __shared__ float red[256];
    red[t] = acc; __syncthreads();
    if (stripe == 0)
        out[((long long)b * SS + i) * 64 + o] = red[t] + red[t + 1] + red[t + 2] + red[t + 3];
}

// ---------------- ctx_ra += einsum('bihr,hdr->bihd', attrel, wr) ----------------
__global__ void relout_k(const float* __restrict__ attrel, const float* __restrict__ wr,
                         float* __restrict__ ctx)
{
    size_t idx = (size_t)blockIdx.x * blockDim.x + threadIdx.x;
    if (idx >= (size_t)MTOT * 512) return;
    int d = idx & 63;
    int h = (idx >> 6) & 7;
    size_t bi = idx >> 9;
    const float* ar = attrel + bi * 64 + h * 8;
    const float* w = wr + ((size_t)h * 64 + d) * 8;
    float v = 0.f;
#pragma unroll
    for (int r = 0; r < 8; r++) v += ar[r] * w[r];
    ctx[idx] += v;
}

// ---------------- launcher ----------------
extern "C" void kernel_launch(void* const* d_in, const int* in_sizes, int n_in,
                              void* d_out, int out_size)
{
    const float* x     = (const float*)d_in[0];
    const float* symb  = (const float*)d_in[1];
    const float* fc    = (const float*)d_in[2];
    const float* fs    = (const float*)d_in[3];
    const float* wq_sa = (const float*)d_in[4];
    const float* wk_sa = (const float*)d_in[5];
    const float* wv_sa = (const float*)d_in[6];
    const float* wo_sa = (const float*)d_in[7];
    const float* wq_at = (const float*)d_in[8];
    const float* wk_at = (const float*)d_in[9];
    const float* wq_rl = (const float*)d_in[10];
    const float* wk_rl = (const float*)d_in[11];
    const float* wr    = (const float*)d_in[12];
    const float* wv_ra = (const float*)d_in[13];
    const float* wo_ra = (const float*)d_in[14];
    float* out = (float*)d_out;

    float *wcat, *proj, *sv, *sc_sa, *sc_ra, *rel, *ctx_sa, *ctx_ra, *attrel;
    cudaGetSymbolAddress((void**)&wcat,   g_wcat);
    cudaGetSymbolAddress((void**)&proj,   g_proj);
    cudaGetSymbolAddress((void**)&sv,     g_sv);
    cudaGetSymbolAddress((void**)&sc_sa,  g_sc_sa);
    cudaGetSymbolAddress((void**)&sc_ra,  g_sc_ra);
    cudaGetSymbolAddress((void**)&rel,    g_rel);
    cudaGetSymbolAddress((void**)&ctx_sa, g_ctx_sa);
    cudaGetSymbolAddress((void**)&ctx_ra, g_ctx_ra);
    cudaGetSymbolAddress((void**)&attrel, g_attrel);

    dim3 tpb(256);
    const float scl = 0.125f;             // 1/sqrt(64), both attn and rel
    const long long bS  = (long long)SS * PLD;     // per-batch stride in proj
    const long long sHS = (long long)SS * SS;      // per-head score stride
    const long long sBS = (long long)HH * SS * SS; // per-batch score stride

    // fused input projections: proj = x @ Wcat^T  (4096 x 3584)
    copy_wcat_k<<<14336, 256>>>(wq_sa, wk_sa, wv_sa, wq_at, wk_at, wq_rl, wk_rl, wcat);
    gemm_k<true, false, false><<<dim3(28, 32, 1), tpb>>>(
        x, DM, 0, 0, wcat, DM, 0, 0, proj, PLD, 0, 0, MTOT, PLD, DM, 1, 1.0f);
    // sv = symbols @ wv_ra^T
    gemm_k<true, false, false><<<dim3(4, 32, 1), tpb>>>(
        symb, DM, 0, 0, wv_ra, DM, 0, 0, sv, 512, 0, 0, MTOT, 512, DM, 1, 1.0f);
    // RoPE on q_sa, k_sa, qa, ka
    rope_k<<<16384, 256>>>(proj, fc, fs);

    // causal score GEMMs (scale folded in)
    gemm_k<true, true, false><<<dim3(16, 16, 16), tpb>>>(
        proj + 0 * 512, PLD, bS, 64, proj + 1 * 512, PLD, bS, 64,
        sc_sa, SS, sBS, sHS, SS, SS, 64, HH, scl);
    gemm_k<true, true, false><<<dim3(16, 16, 16), tpb>>>(
        proj + 3 * 512, PLD, bS, 64, proj + 4 * 512, PLD, bS, 64,
        sc_ra, SS, sBS, sHS, SS, SS, 64, HH, scl);
    gemm_k<true, true, false><<<dim3(16, 16, 16), tpb>>>(
        proj + 5 * 512, PLD, bS, 64, proj + 6 * 512, PLD, bS, 64,
        rel, SS, (long long)NREL * SS * SS, sHS, SS, SS, 64, NREL, scl);

    // in-place softmax -> alpha
    softmax_k<<<dim3(SS, BB * HH), 256>>>(sc_sa);
    softmax_k<<<dim3(SS, BB * HH), 256>>>(sc_ra);

    // ctx = alpha @ V (K-clamped to the causal range)
    gemm_k<false, false, true><<<dim3(1, 16, 16), tpb>>>(
        sc_sa, SS, sBS, sHS, proj + 2 * 512, PLD, bS, 64,
        ctx_sa, 512, (long long)SS * 512, 64, SS, 64, SS, HH, 1.0f);
    gemm_k<false, false, true><<<dim3(1, 16, 16), tpb>>>(
        sc_ra, SS, sBS, sHS, sv, 512, (long long)SS * 512, 64,
        ctx_ra, 512, (long long)SS * 512, 64, SS, 64, SS, HH, 1.0f);

    // attended_rel, then += wr contraction
    attrel_k<<<dim3(SS, BB), 256>>>(sc_ra, rel, attrel);
    relout_k<<<8192, 256>>>(attrel, wr, ctx_ra);

    // output projections, concatenated into d_out
    gemm_k<true, false, false><<<dim3(4, 32, 1), tpb>>>(
        ctx_sa, 512, 0, 0, wo_sa, 512, 0, 0, out, DM, 0, 0, MTOT, 512, 512, 1, 1.0f);
    gemm_k<true, false, false><<<dim3(4, 32, 1), tpb>>>(
        ctx_ra, 512, 0, 0, wo_ra, 512, 0, 0, out + 512, DM, 0, 0, MTOT, 512, 512, 1, 1.0f);
}